// round 2
// baseline (speedup 1.0000x reference)
#include <cuda_runtime.h>

// ---------------------------------------------------------------------------
// TimeSeriesRNN: 2-layer LSTM encoder-decoder, persistent-kernel fp32 baseline
//   B=64, T_IN=256, V=64, H=1024, T_OUT=32
// Single persistent kernel, 128 CTAs x 256 threads, software grid barrier.
// GEMM inner loops use packed fma.rn.f32x2 (2x fp32 FMA per instruction).
// ---------------------------------------------------------------------------

#define B_       64
#define TIN_     256
#define V_       64
#define H_       1024
#define G4_      4096
#define TOUT_    32
#define NCTA     128
#define NTHREADS 256
#define CHPC     8   // hidden channels owned per CTA (8 * 128 = 1024)

typedef unsigned long long u64;

// ------------------------- device scratch (static) -------------------------
__device__ float g_xt[TIN_ * V_ * B_];                 // x transposed: [t][v][b]
__device__ float g_h0all[(size_t)TIN_ * H_ * B_];      // layer0 h history [t][j][b]
__device__ float g_c0[H_ * B_];
__device__ float g_c1[H_ * B_];
__device__ float g_h1[2][H_ * B_];                     // layer1 encoder ping-pong
__device__ float g_dh0[2][H_ * B_];                    // decoder layer0 ping-pong
__device__ float g_dh1[2][H_ * B_];                    // decoder layer1 ping-pong
__device__ float g_dec_in[V_ * B_];                    // decoder feed-back input [v][b]

__device__ unsigned g_bar_count = 0;
__device__ volatile unsigned g_bar_gen = 0;

// ------------------------------ grid barrier -------------------------------
__device__ __forceinline__ void grid_barrier() {
    __syncthreads();
    if (threadIdx.x == 0) {
        unsigned gen = g_bar_gen;
        __threadfence();
        unsigned ticket = atomicAdd(&g_bar_count, 1u);
        if (ticket == NCTA - 1) {
            g_bar_count = 0;
            __threadfence();
            g_bar_gen = gen + 1;
        } else {
            while (g_bar_gen == gen) { }
        }
        __threadfence();
    }
    __syncthreads();
}

// --------------------------- packed f32x2 helpers --------------------------
__device__ __forceinline__ u64 pack2(float lo, float hi) {
    u64 r;
    asm("mov.b64 %0, {%1, %2};" : "=l"(r) : "f"(lo), "f"(hi));
    return r;
}
__device__ __forceinline__ void unpack2(u64 v, float &lo, float &hi) {
    asm("mov.b64 {%0, %1}, %2;" : "=f"(lo), "=f"(hi) : "l"(v));
}
__device__ __forceinline__ void fma2(u64 &d, u64 a, u64 b) {
    asm("fma.rn.f32x2 %0, %1, %2, %0;" : "+l"(d) : "l"(a), "l"(b));
}

// ---------------------------------------------------------------------------
// Accumulate acc[4] (4 packed pairs = 8 batch elements of one gate row)
//   acc += W[r][koff + k] * in[k][b0..b0+7]  for k in [0, K)
// in is [K][B_] row-major; wrow = W + r*ldw + koff.
// All 256 threads of the CTA participate (uniform K).
// ---------------------------------------------------------------------------
__device__ __forceinline__ void accum_seg(
    u64 acc[4],
    const float* __restrict__ in, int K,
    const float* __restrict__ wrow,
    float* s_in, int b0, int tid)
{
    float4 tin[4];
    {
        const float4* src = (const float4*)in;
        #pragma unroll
        for (int i = 0; i < 4; i++) tin[i] = src[tid + i * 256];
    }
    for (int kt = 0; kt < K; kt += 64) {
        __syncthreads();                       // previous tile fully consumed
        {
            float4* dst = (float4*)s_in;
            #pragma unroll
            for (int i = 0; i < 4; i++) dst[tid + i * 256] = tin[i];
        }
        __syncthreads();
        if (kt + 64 < K) {                     // prefetch next tile into regs
            const float4* nsrc = (const float4*)(in + (size_t)(kt + 64) * B_);
            #pragma unroll
            for (int i = 0; i < 4; i++) tin[i] = nsrc[tid + i * 256];
        }
        // preload this tile's 64 weights (16 x LDG.128, deep MLP)
        const float4* w4p = (const float4*)(wrow + kt);
        float4 w4[16];
        #pragma unroll
        for (int i = 0; i < 16; i++) w4[i] = w4p[i];

        #pragma unroll
        for (int kq = 0; kq < 16; kq++) {
            float wv0 = w4[kq].x, wv1 = w4[kq].y, wv2 = w4[kq].z, wv3 = w4[kq].w;
            #pragma unroll
            for (int kk = 0; kk < 4; kk++) {
                float wv = (kk == 0) ? wv0 : (kk == 1) ? wv1 : (kk == 2) ? wv2 : wv3;
                u64 wp = pack2(wv, wv);
                const u64* sp = (const u64*)(s_in + (kq * 4 + kk) * B_ + b0);
                ulonglong2 q0 = *(const ulonglong2*)(sp);
                ulonglong2 q1 = *(const ulonglong2*)(sp + 2);
                fma2(acc[0], wp, q0.x);
                fma2(acc[1], wp, q0.y);
                fma2(acc[2], wp, q1.x);
                fma2(acc[3], wp, q1.y);
            }
        }
    }
}

// ---------------------------------------------------------------------------
// One LSTM step for the CTA's 8 channels (32 gate rows), all 64 batches.
//   gates = bias + in1 @ W[:, koff1:koff1+K1].T + in2 @ W[:, koff2:koff2+K2].T
//   c = sig(f)*c + sig(i)*tanh(ct);  h_out = sig(o)*tanh(c)
// ---------------------------------------------------------------------------
__device__ void lstm_gate_step(
    const float* __restrict__ bias,
    const float* __restrict__ in1, int K1, int koff1,
    const float* __restrict__ in2, int K2, int koff2,
    const float* __restrict__ W, int ldw,
    float* __restrict__ c,
    float* __restrict__ h_out,
    float* s_in, float* s_gates)
{
    const int tid = threadIdx.x;
    const int row_slot = tid >> 3;      // 0..31
    const int g  = row_slot >> 3;       // gate: 0=i 1=f 2=ct 3=o
    const int jj = row_slot & 7;        // channel within CTA
    const int bgrp = tid & 7;
    const int b0 = bgrp * 8;
    const int j0 = blockIdx.x * CHPC;
    const int r = g * H_ + j0 + jj;     // gate row in [0, 4096)

    u64 acc[4];
    {
        float bv = bias[r];
        u64 bp = pack2(bv, bv);
        acc[0] = bp; acc[1] = bp; acc[2] = bp; acc[3] = bp;
    }

    if (K1 > 0) accum_seg(acc, in1, K1, W + (size_t)r * ldw + koff1, s_in, b0, tid);
    if (K2 > 0) accum_seg(acc, in2, K2, W + (size_t)r * ldw + koff2, s_in, b0, tid);

    __syncthreads();
    {
        float* gdst = s_gates + (g * CHPC + jj) * B_ + b0;
        #pragma unroll
        for (int i = 0; i < 4; i++) {
            float lo, hi; unpack2(acc[i], lo, hi);
            gdst[2 * i]     = lo;
            gdst[2 * i + 1] = hi;
        }
    }
    __syncthreads();

    // cell update: CHPC*B = 512 elements, CTA-local
    for (int e = tid; e < CHPC * B_; e += NTHREADS) {
        int jjj = e >> 6;
        int b   = e & 63;
        float gi = s_gates[(0 * CHPC + jjj) * B_ + b];
        float gf = s_gates[(1 * CHPC + jjj) * B_ + b];
        float gc = s_gates[(2 * CHPC + jjj) * B_ + b];
        float go = s_gates[(3 * CHPC + jjj) * B_ + b];
        int idx = (j0 + jjj) * B_ + b;
        float cc = c[idx];
        float si = 1.0f / (1.0f + expf(-gi));
        float sf = 1.0f / (1.0f + expf(-gf));
        float so = 1.0f / (1.0f + expf(-go));
        float cn = sf * cc + si * tanhf(gc);
        float hn = so * tanhf(cn);
        c[idx] = cn;
        h_out[idx] = hn;
    }
}

// --------------------------------- kernel ----------------------------------
__global__ void __launch_bounds__(NTHREADS, 1)
rnn_kernel(const float* __restrict__ x,
           const float* __restrict__ W0, const float* __restrict__ b0,
           const float* __restrict__ W1, const float* __restrict__ b1,
           const float* __restrict__ Wf, const float* __restrict__ bf,
           float* __restrict__ out)
{
    __shared__ float s_in[64 * B_];          // 16 KB input tile [k][b]
    __shared__ float s_gates[4 * CHPC * B_]; // 8 KB gate exchange

    const int tid = threadIdx.x;
    const int cta = blockIdx.x;

    // ---- Phase 0: init states + transpose x into [t][v][b] ----
    for (int i = cta * NTHREADS + tid; i < H_ * B_; i += NCTA * NTHREADS) {
        g_c0[i] = 0.0f; g_c1[i] = 0.0f;
    }
    for (int i = cta * NTHREADS + tid; i < TIN_ * V_ * B_; i += NCTA * NTHREADS) {
        int t = i / (V_ * B_);
        int rem = i - t * (V_ * B_);
        int v = rem >> 6;       // / B_
        int b = rem & 63;
        g_xt[i] = x[((size_t)b * TIN_ + t) * V_ + v];
    }
    grid_barrier();

    // ---- Encoder layer 0: gates = [x_t, h] @ W0.T + b0 ----
    for (int t = 0; t < TIN_; t++) {
        lstm_gate_step(b0,
                       g_xt + (size_t)t * V_ * B_, V_, 0,
                       (t > 0) ? (g_h0all + (size_t)(t - 1) * H_ * B_) : (const float*)0,
                       (t > 0) ? H_ : 0, V_,
                       W0, V_ + H_,
                       g_c0,
                       g_h0all + (size_t)t * H_ * B_,
                       s_in, s_gates);
        grid_barrier();
    }

    // ---- Encoder layer 1: gates = [h0_t, h1] @ W1.T + b1 ----
    for (int t = 0; t < TIN_; t++) {
        lstm_gate_step(b1,
                       g_h0all + (size_t)t * H_ * B_, H_, 0,
                       (t > 0) ? g_h1[t & 1] : (const float*)0,
                       (t > 0) ? H_ : 0, H_,
                       W1, 2 * H_,
                       g_c1,
                       g_h1[(t + 1) & 1],
                       s_in, s_gates);
        grid_barrier();
    }

    // ---- Decoder: T_OUT steps, feed output back as input ----
    for (int s = 0; s < TOUT_; s++) {
        const float* in0 = (s == 0) ? (g_xt + (size_t)(TIN_ - 1) * V_ * B_) : g_dec_in;
        const float* h0p = (s == 0) ? (g_h0all + (size_t)(TIN_ - 1) * H_ * B_) : g_dh0[s & 1];
        lstm_gate_step(b0, in0, V_, 0, h0p, H_, V_, W0, V_ + H_,
                       g_c0, g_dh0[(s + 1) & 1], s_in, s_gates);
        grid_barrier();

        const float* h1p = (s == 0) ? g_h1[0] : g_dh1[s & 1];
        lstm_gate_step(b1, g_dh0[(s + 1) & 1], H_, 0, h1p, H_, H_, W1, 2 * H_,
                       g_c1, g_dh1[(s + 1) & 1], s_in, s_gates);
        grid_barrier();

        // projection: out = h1 @ Wf.T + bf  (4096 outputs over 128 CTAs)
        {
            const float* h1 = g_dh1[(s + 1) & 1];
            int o  = cta * 32 + (tid >> 3);     // output index in [0, 4096)
            int ko = tid & 7;                   // k-lane within 8-thread group
            int v = o >> 6;                     // / 64
            int b = o & 63;
            float sum = 0.0f;
            for (int k = ko; k < H_; k += 8)
                sum += h1[k * B_ + b] * Wf[v * H_ + k];
            sum += __shfl_down_sync(0xFFFFFFFFu, sum, 4, 8);
            sum += __shfl_down_sync(0xFFFFFFFFu, sum, 2, 8);
            sum += __shfl_down_sync(0xFFFFFFFFu, sum, 1, 8);
            if (ko == 0) {
                float val = sum + bf[v];
                out[((size_t)b * TOUT_ + s) * V_ + v] = val;
                g_dec_in[v * B_ + b] = val;
            }
        }
        grid_barrier();
    }
}

// ------------------------------ launch shim --------------------------------
extern "C" void kernel_launch(void* const* d_in, const int* in_sizes, int n_in,
                              void* d_out, int out_size) {
    const float* x  = (const float*)d_in[0];
    const float* W0 = (const float*)d_in[1];
    const float* b0 = (const float*)d_in[2];
    const float* W1 = (const float*)d_in[3];
    const float* b1 = (const float*)d_in[4];
    const float* Wf = (const float*)d_in[5];
    const float* bf = (const float*)d_in[6];
    rnn_kernel<<<NCTA, NTHREADS>>>(x, W0, b0, W1, b1, Wf, bf, (float*)d_out);
}

// round 6
// speedup vs baseline: 2.2919x; 2.2919x over previous
#include <cuda_runtime.h>

// ---------------------------------------------------------------------------
// TimeSeriesRNN: 2-layer LSTM encoder-decoder, persistent-kernel fp32
//   B=64, T_IN=256, V=64, H=1024, T_OUT=32
// R3: register-blocked 2 rows x 4 batches per thread, weights staged in smem,
//     conflict-free input LDS.128 -> packed fma.rn.f32x2 at the FFMA2 floor.
// ---------------------------------------------------------------------------

#define B_       64
#define TIN_     256
#define V_       64
#define H_       1024
#define TOUT_    32
#define NCTA     128
#define NTHREADS 256
#define CHPC     8        // hidden channels per CTA (8 * 128 = 1024)
#define WST      132      // padded smem row stride (floats) for weight tile

typedef unsigned long long u64;

// ------------------------- device scratch (static) -------------------------
__device__ float g_xt[TIN_ * V_ * B_];                 // x transposed [t][v][b]
__device__ float g_h0all[(size_t)TIN_ * H_ * B_];      // layer0 h history [t][j][b]
__device__ float g_c0[H_ * B_];
__device__ float g_c1[H_ * B_];
__device__ float g_h1[2][H_ * B_];
__device__ float g_dh0[2][H_ * B_];
__device__ float g_dh1[2][H_ * B_];
__device__ float g_dec_in[V_ * B_];

__device__ unsigned g_bar_count = 0;
__device__ volatile unsigned g_bar_gen = 0;

// ------------------------------ grid barrier -------------------------------
__device__ __forceinline__ void grid_barrier() {
    __syncthreads();
    if (threadIdx.x == 0) {
        unsigned gen = g_bar_gen;
        __threadfence();
        unsigned ticket = atomicAdd(&g_bar_count, 1u);
        if (ticket == NCTA - 1) {
            g_bar_count = 0;
            __threadfence();
            g_bar_gen = gen + 1;
        } else {
            while (g_bar_gen == gen) { }
        }
        __threadfence();
    }
    __syncthreads();
}

// --------------------------- packed f32x2 helpers --------------------------
__device__ __forceinline__ u64 pack2(float lo, float hi) {
    u64 r;
    asm("mov.b64 %0, {%1, %2};" : "=l"(r) : "f"(lo), "f"(hi));
    return r;
}
__device__ __forceinline__ void unpack2(u64 v, float &lo, float &hi) {
    asm("mov.b64 {%0, %1}, %2;" : "=f"(lo), "=f"(hi) : "l"(v));
}
__device__ __forceinline__ void fma2(u64 &d, u64 a, u64 b) {
    asm("fma.rn.f32x2 %0, %1, %2, %0;" : "+l"(d) : "l"(a), "l"(b));
}

// ---------------------------------------------------------------------------
// Compute one staged K-tile: acc{A,B}[2] += w_row{A,B}[k] * in[k][B0..B0+3]
// s_in: [ktcur][64] floats;  s_w: [32 rows][WST] floats.
// ---------------------------------------------------------------------------
__device__ __forceinline__ void compute_tile(
    u64 accA[2], u64 accB[2],
    const float* __restrict__ s_in, const float* __restrict__ s_w,
    int R0, int B0, int ktcur)
{
    const float* wr0 = s_w + R0 * WST;
    const float* wr1 = wr0 + WST;
    #pragma unroll 4
    for (int k = 0; k < ktcur; k += 4) {
        float4 wa = *(const float4*)(wr0 + k);
        float4 wb = *(const float4*)(wr1 + k);
        #pragma unroll
        for (int kk = 0; kk < 4; kk++) {
            ulonglong2 xx = *(const ulonglong2*)(s_in + (k + kk) * 64 + B0);
            float wav = (kk == 0) ? wa.x : (kk == 1) ? wa.y : (kk == 2) ? wa.z : wa.w;
            float wbv = (kk == 0) ? wb.x : (kk == 1) ? wb.y : (kk == 2) ? wb.z : wb.w;
            u64 wap = pack2(wav, wav);
            u64 wbp = pack2(wbv, wbv);
            fma2(accA[0], wap, xx.x);
            fma2(accA[1], wap, xx.y);
            fma2(accB[0], wbp, xx.x);
            fma2(accB[1], wbp, xx.y);
        }
    }
}

// ---------------------------------------------------------------------------
// Accumulate a K=1024 segment (8 tiles of 128) with reg-prefetch double buffer.
// in: [1024][64]; wseg = W + r_ld*ldw + koff (this thread's staging row).
// ---------------------------------------------------------------------------
__device__ __forceinline__ void accum_1024(
    u64 accA[2], u64 accB[2],
    const float* __restrict__ in,
    const float* __restrict__ wseg,
    float* s_in, float* s_w,
    int tid, int rs_ld, int k8, int R0, int B0)
{
    const float4* in4 = (const float4*)in;
    float4 pin[8];
    float4 pw[4];
    #pragma unroll
    for (int i = 0; i < 8; i++) pin[i] = in4[tid + i * 256];
    #pragma unroll
    for (int i = 0; i < 4; i++) pw[i] = *(const float4*)(wseg + k8 * 4 + i * 32);

    for (int kt = 0; kt < 1024; kt += 128) {
        __syncthreads();
        #pragma unroll
        for (int i = 0; i < 8; i++) ((float4*)s_in)[tid + i * 256] = pin[i];
        #pragma unroll
        for (int i = 0; i < 4; i++)
            *(float4*)(s_w + rs_ld * WST + k8 * 4 + i * 32) = pw[i];
        __syncthreads();
        if (kt + 128 < 1024) {
            #pragma unroll
            for (int i = 0; i < 8; i++) pin[i] = in4[(kt + 128) * 16 + tid + i * 256];
            #pragma unroll
            for (int i = 0; i < 4; i++)
                pw[i] = *(const float4*)(wseg + kt + 128 + k8 * 4 + i * 32);
        }
        compute_tile(accA, accB, s_in, s_w, R0, B0, 128);
    }
}

// ---------------------------------------------------------------------------
// Accumulate a K=64 segment (single 64-tile).
// ---------------------------------------------------------------------------
__device__ __forceinline__ void accum_64(
    u64 accA[2], u64 accB[2],
    const float* __restrict__ in,
    const float* __restrict__ wseg,
    float* s_in, float* s_w,
    int tid, int rs_ld, int k8, int R0, int B0)
{
    const float4* in4 = (const float4*)in;
    float4 pin[4];
    float4 pw[2];
    #pragma unroll
    for (int i = 0; i < 4; i++) pin[i] = in4[tid + i * 256];
    #pragma unroll
    for (int i = 0; i < 2; i++) pw[i] = *(const float4*)(wseg + k8 * 4 + i * 32);

    __syncthreads();
    #pragma unroll
    for (int i = 0; i < 4; i++) ((float4*)s_in)[tid + i * 256] = pin[i];
    #pragma unroll
    for (int i = 0; i < 2; i++)
        *(float4*)(s_w + rs_ld * WST + k8 * 4 + i * 32) = pw[i];
    __syncthreads();
    compute_tile(accA, accB, s_in, s_w, R0, B0, 64);
}

// ---------------------------------------------------------------------------
// One LSTM step for the CTA's 8 channels (32 gate rows), all 64 batches.
// ---------------------------------------------------------------------------
__device__ void lstm_step(
    const float* __restrict__ bias,
    const float* __restrict__ in1, int K1,          // 64 or 1024
    const float* __restrict__ in2, bool has2, int koff2,
    const float* __restrict__ W, int ldw,
    float* __restrict__ c, float* __restrict__ h_out,
    float* s_in, float* s_w, float* s_gates, int j0)
{
    const int tid = threadIdx.x;
    const int w   = tid >> 5;
    const int l   = tid & 31;
    const int rh  = w & 1;
    const int bq  = w >> 1;
    const int rp  = l & 7;
    const int bg  = l >> 3;
    const int R0  = 16 * rh + 2 * rp;      // thread rows R0, R0+1 (row slots)
    const int B0  = 16 * bq + 4 * bg;      // thread batches B0..B0+3

    const int rs_ld = tid >> 3;            // staging row slot (0..31)
    const int k8    = tid & 7;             // staging k-lane
    const int r_ld  = (rs_ld >> 3) * H_ + j0 + (rs_ld & 7);   // gmem row
    const float* wrow_ld = W + (size_t)r_ld * ldw;

    const int rA = (R0 >> 3) * H_ + j0 + (R0 & 7);
    const int rB = ((R0 + 1) >> 3) * H_ + j0 + ((R0 + 1) & 7);

    u64 accA[2], accB[2];
    {
        float ba = bias[rA], bb = bias[rB];
        accA[0] = accA[1] = pack2(ba, ba);
        accB[0] = accB[1] = pack2(bb, bb);
    }

    if (K1 == 64)
        accum_64(accA, accB, in1, wrow_ld, s_in, s_w, tid, rs_ld, k8, R0, B0);
    else
        accum_1024(accA, accB, in1, wrow_ld, s_in, s_w, tid, rs_ld, k8, R0, B0);

    if (has2)
        accum_1024(accA, accB, in2, wrow_ld + koff2, s_in, s_w, tid, rs_ld, k8, R0, B0);

    __syncthreads();
    {
        float lo, hi;
        unpack2(accA[0], lo, hi); *(float2*)&s_gates[R0 * 64 + B0]       = make_float2(lo, hi);
        unpack2(accA[1], lo, hi); *(float2*)&s_gates[R0 * 64 + B0 + 2]   = make_float2(lo, hi);
        unpack2(accB[0], lo, hi); *(float2*)&s_gates[(R0 + 1) * 64 + B0]     = make_float2(lo, hi);
        unpack2(accB[1], lo, hi); *(float2*)&s_gates[(R0 + 1) * 64 + B0 + 2] = make_float2(lo, hi);
    }
    __syncthreads();

    // cell update: CHPC*B = 512 elements, CTA-local
    for (int e = tid; e < CHPC * B_; e += NTHREADS) {
        int jjj = e >> 6;
        int b   = e & 63;
        float gi = s_gates[(0 * CHPC + jjj) * 64 + b];
        float gf = s_gates[(1 * CHPC + jjj) * 64 + b];
        float gc = s_gates[(2 * CHPC + jjj) * 64 + b];
        float go = s_gates[(3 * CHPC + jjj) * 64 + b];
        int idx = (j0 + jjj) * B_ + b;
        float cc = c[idx];
        float si = 1.0f / (1.0f + expf(-gi));
        float sf = 1.0f / (1.0f + expf(-gf));
        float so = 1.0f / (1.0f + expf(-go));
        float cn = sf * cc + si * tanhf(gc);
        float hn = so * tanhf(cn);
        c[idx] = cn;
        h_out[idx] = hn;
    }
}

// --------------------------------- kernel ----------------------------------
__global__ void __launch_bounds__(NTHREADS, 1)
rnn_kernel(const float* __restrict__ x,
           const float* __restrict__ W0, const float* __restrict__ b0,
           const float* __restrict__ W1, const float* __restrict__ b1,
           const float* __restrict__ Wf, const float* __restrict__ bf,
           float* __restrict__ out)
{
    extern __shared__ float smem[];
    float* s_in    = smem;                    // 128*64 = 8192 floats
    float* s_w     = s_in + 128 * 64;         // 32*WST = 4224 floats
    float* s_gates = s_w + 32 * WST;          // 32*64  = 2048 floats

    const int tid = threadIdx.x;
    const int cta = blockIdx.x;
    const int j0  = cta * CHPC;

    // ---- Phase 0: init states + transpose x into [t][v][b] ----
    for (int i = cta * NTHREADS + tid; i < H_ * B_; i += NCTA * NTHREADS) {
        g_c0[i] = 0.0f; g_c1[i] = 0.0f;
    }
    for (int i = cta * NTHREADS + tid; i < TIN_ * V_ * B_; i += NCTA * NTHREADS) {
        int t = i / (V_ * B_);
        int rem = i - t * (V_ * B_);
        int v = rem >> 6;
        int b = rem & 63;
        g_xt[i] = x[((size_t)b * TIN_ + t) * V_ + v];
    }
    grid_barrier();

    // ---- Encoder layer 0 ----
    for (int t = 0; t < TIN_; t++) {
        lstm_step(b0,
                  g_xt + (size_t)t * V_ * B_, V_,
                  (t > 0) ? (g_h0all + (size_t)(t - 1) * H_ * B_) : (const float*)0,
                  t > 0, V_,
                  W0, V_ + H_,
                  g_c0, g_h0all + (size_t)t * H_ * B_,
                  s_in, s_w, s_gates, j0);
        grid_barrier();
    }

    // ---- Encoder layer 1 ----
    for (int t = 0; t < TIN_; t++) {
        lstm_step(b1,
                  g_h0all + (size_t)t * H_ * B_, H_,
                  (t > 0) ? g_h1[t & 1] : (const float*)0,
                  t > 0, H_,
                  W1, 2 * H_,
                  g_c1, g_h1[(t + 1) & 1],
                  s_in, s_w, s_gates, j0);
        grid_barrier();
    }

    // ---- Decoder ----
    for (int s = 0; s < TOUT_; s++) {
        const float* in0 = (s == 0) ? (g_xt + (size_t)(TIN_ - 1) * V_ * B_) : g_dec_in;
        const float* h0p = (s == 0) ? (g_h0all + (size_t)(TIN_ - 1) * H_ * B_) : g_dh0[s & 1];
        lstm_step(b0, in0, V_, h0p, true, V_, W0, V_ + H_,
                  g_c0, g_dh0[(s + 1) & 1], s_in, s_w, s_gates, j0);
        grid_barrier();

        const float* h1p = (s == 0) ? g_h1[0] : g_dh1[s & 1];
        lstm_step(b1, g_dh0[(s + 1) & 1], H_, h1p, true, H_, W1, 2 * H_,
                  g_c1, g_dh1[(s + 1) & 1], s_in, s_w, s_gates, j0);
        grid_barrier();

        // projection: out = h1 @ Wf.T + bf  (4096 outputs over 128 CTAs)
        {
            const float* h1 = g_dh1[(s + 1) & 1];
            int o  = cta * 32 + (tid >> 3);
            int ko = tid & 7;
            int v = o >> 6;
            int b = o & 63;
            float sum = 0.0f;
            for (int k = ko; k < H_; k += 8)
                sum += h1[k * B_ + b] * Wf[v * H_ + k];
            sum += __shfl_down_sync(0xFFFFFFFFu, sum, 4, 8);
            sum += __shfl_down_sync(0xFFFFFFFFu, sum, 2, 8);
            sum += __shfl_down_sync(0xFFFFFFFFu, sum, 1, 8);
            if (ko == 0) {
                float val = sum + bf[v];
                out[((size_t)b * TOUT_ + s) * V_ + v] = val;
                g_dec_in[v * B_ + b] = val;
            }
        }
        grid_barrier();
    }
}

// ------------------------------ launch shim --------------------------------
extern "C" void kernel_launch(void* const* d_in, const int* in_sizes, int n_in,
                              void* d_out, int out_size) {
    const float* x  = (const float*)d_in[0];
    const float* W0 = (const float*)d_in[1];
    const float* b0 = (const float*)d_in[2];
    const float* W1 = (const float*)d_in[3];
    const float* b1 = (const float*)d_in[4];
    const float* Wf = (const float*)d_in[5];
    const float* bf = (const float*)d_in[6];

    const int smem_bytes = (128 * 64 + 32 * WST + 32 * 64) * (int)sizeof(float);
    cudaFuncSetAttribute(rnn_kernel, cudaFuncAttributeMaxDynamicSharedMemorySize,
                         smem_bytes);
    rnn_kernel<<<NCTA, NTHREADS, smem_bytes>>>(x, W0, b0, W1, b1, Wf, bf,
                                               (float*)d_out);
}

// round 7
// speedup vs baseline: 2.4133x; 1.0529x over previous
#include <cuda_runtime.h>

// ---------------------------------------------------------------------------
// TimeSeriesRNN: 2-layer LSTM encoder-decoder, persistent-kernel fp32
//   B=64, T_IN=256, V=64, H=1024, T_OUT=32
// R3: register-blocked 2 rows x 4 batches per thread, weights staged in smem,
//     conflict-free input LDS.128 -> packed fma.rn.f32x2 at the FFMA2 floor.
// ---------------------------------------------------------------------------

#define B_       64
#define TIN_     256
#define V_       64
#define H_       1024
#define TOUT_    32
#define NCTA     128
#define NTHREADS 256
#define CHPC     8        // hidden channels per CTA (8 * 128 = 1024)
#define WST      132      // padded smem row stride (floats) for weight tile

typedef unsigned long long u64;

// ------------------------- device scratch (static) -------------------------
__device__ float g_xt[TIN_ * V_ * B_];                 // x transposed [t][v][b]
__device__ float g_h0all[(size_t)TIN_ * H_ * B_];      // layer0 h history [t][j][b]
__device__ float g_c0[H_ * B_];
__device__ float g_c1[H_ * B_];
__device__ float g_h1[2][H_ * B_];
__device__ float g_dh0[2][H_ * B_];
__device__ float g_dh1[2][H_ * B_];
__device__ float g_dec_in[V_ * B_];

__device__ unsigned g_bar_count = 0;
__device__ volatile unsigned g_bar_gen = 0;

// ------------------------------ grid barrier -------------------------------
__device__ __forceinline__ void grid_barrier() {
    __syncthreads();
    if (threadIdx.x == 0) {
        unsigned gen = g_bar_gen;
        __threadfence();
        unsigned ticket = atomicAdd(&g_bar_count, 1u);
        if (ticket == NCTA - 1) {
            g_bar_count = 0;
            __threadfence();
            g_bar_gen = gen + 1;
        } else {
            while (g_bar_gen == gen) { }
        }
        __threadfence();
    }
    __syncthreads();
}

// --------------------------- packed f32x2 helpers --------------------------
__device__ __forceinline__ u64 pack2(float lo, float hi) {
    u64 r;
    asm("mov.b64 %0, {%1, %2};" : "=l"(r) : "f"(lo), "f"(hi));
    return r;
}
__device__ __forceinline__ void unpack2(u64 v, float &lo, float &hi) {
    asm("mov.b64 {%0, %1}, %2;" : "=f"(lo), "=f"(hi) : "l"(v));
}
__device__ __forceinline__ void fma2(u64 &d, u64 a, u64 b) {
    asm("fma.rn.f32x2 %0, %1, %2, %0;" : "+l"(d) : "l"(a), "l"(b));
}

// ---------------------------------------------------------------------------
// Compute one staged K-tile: acc{A,B}[2] += w_row{A,B}[k] * in[k][B0..B0+3]
// s_in: [ktcur][64] floats;  s_w: [32 rows][WST] floats.
// ---------------------------------------------------------------------------
__device__ __forceinline__ void compute_tile(
    u64 accA[2], u64 accB[2],
    const float* __restrict__ s_in, const float* __restrict__ s_w,
    int R0, int B0, int ktcur)
{
    const float* wr0 = s_w + R0 * WST;
    const float* wr1 = wr0 + WST;
    #pragma unroll 4
    for (int k = 0; k < ktcur; k += 4) {
        float4 wa = *(const float4*)(wr0 + k);
        float4 wb = *(const float4*)(wr1 + k);
        #pragma unroll
        for (int kk = 0; kk < 4; kk++) {
            ulonglong2 xx = *(const ulonglong2*)(s_in + (k + kk) * 64 + B0);
            float wav = (kk == 0) ? wa.x : (kk == 1) ? wa.y : (kk == 2) ? wa.z : wa.w;
            float wbv = (kk == 0) ? wb.x : (kk == 1) ? wb.y : (kk == 2) ? wb.z : wb.w;
            u64 wap = pack2(wav, wav);
            u64 wbp = pack2(wbv, wbv);
            fma2(accA[0], wap, xx.x);
            fma2(accA[1], wap, xx.y);
            fma2(accB[0], wbp, xx.x);
            fma2(accB[1], wbp, xx.y);
        }
    }
}

// ---------------------------------------------------------------------------
// Accumulate a K=1024 segment (8 tiles of 128) with reg-prefetch double buffer.
// in: [1024][64]; wseg = W + r_ld*ldw + koff (this thread's staging row).
// ---------------------------------------------------------------------------
__device__ __forceinline__ void accum_1024(
    u64 accA[2], u64 accB[2],
    const float* __restrict__ in,
    const float* __restrict__ wseg,
    float* s_in, float* s_w,
    int tid, int rs_ld, int k8, int R0, int B0)
{
    const float4* in4 = (const float4*)in;
    float4 pin[8];
    float4 pw[4];
    #pragma unroll
    for (int i = 0; i < 8; i++) pin[i] = in4[tid + i * 256];
    #pragma unroll
    for (int i = 0; i < 4; i++) pw[i] = *(const float4*)(wseg + k8 * 4 + i * 32);

    for (int kt = 0; kt < 1024; kt += 128) {
        __syncthreads();
        #pragma unroll
        for (int i = 0; i < 8; i++) ((float4*)s_in)[tid + i * 256] = pin[i];
        #pragma unroll
        for (int i = 0; i < 4; i++)
            *(float4*)(s_w + rs_ld * WST + k8 * 4 + i * 32) = pw[i];
        __syncthreads();
        if (kt + 128 < 1024) {
            #pragma unroll
            for (int i = 0; i < 8; i++) pin[i] = in4[(kt + 128) * 16 + tid + i * 256];
            #pragma unroll
            for (int i = 0; i < 4; i++)
                pw[i] = *(const float4*)(wseg + kt + 128 + k8 * 4 + i * 32);
        }
        compute_tile(accA, accB, s_in, s_w, R0, B0, 128);
    }
}

// ---------------------------------------------------------------------------
// Accumulate a K=64 segment (single 64-tile).
// ---------------------------------------------------------------------------
__device__ __forceinline__ void accum_64(
    u64 accA[2], u64 accB[2],
    const float* __restrict__ in,
    const float* __restrict__ wseg,
    float* s_in, float* s_w,
    int tid, int rs_ld, int k8, int R0, int B0)
{
    const float4* in4 = (const float4*)in;
    float4 pin[4];
    float4 pw[2];
    #pragma unroll
    for (int i = 0; i < 4; i++) pin[i] = in4[tid + i * 256];
    #pragma unroll
    for (int i = 0; i < 2; i++) pw[i] = *(const float4*)(wseg + k8 * 4 + i * 32);

    __syncthreads();
    #pragma unroll
    for (int i = 0; i < 4; i++) ((float4*)s_in)[tid + i * 256] = pin[i];
    #pragma unroll
    for (int i = 0; i < 2; i++)
        *(float4*)(s_w + rs_ld * WST + k8 * 4 + i * 32) = pw[i];
    __syncthreads();
    compute_tile(accA, accB, s_in, s_w, R0, B0, 64);
}

// ---------------------------------------------------------------------------
// One LSTM step for the CTA's 8 channels (32 gate rows), all 64 batches.
// ---------------------------------------------------------------------------
__device__ void lstm_step(
    const float* __restrict__ bias,
    const float* __restrict__ in1, int K1,          // 64 or 1024
    const float* __restrict__ in2, bool has2, int koff2,
    const float* __restrict__ W, int ldw,
    float* __restrict__ c, float* __restrict__ h_out,
    float* s_in, float* s_w, float* s_gates, int j0)
{
    const int tid = threadIdx.x;
    const int w   = tid >> 5;
    const int l   = tid & 31;
    const int rh  = w & 1;
    const int bq  = w >> 1;
    const int rp  = l & 7;
    const int bg  = l >> 3;
    const int R0  = 16 * rh + 2 * rp;      // thread rows R0, R0+1 (row slots)
    const int B0  = 16 * bq + 4 * bg;      // thread batches B0..B0+3

    const int rs_ld = tid >> 3;            // staging row slot (0..31)
    const int k8    = tid & 7;             // staging k-lane
    const int r_ld  = (rs_ld >> 3) * H_ + j0 + (rs_ld & 7);   // gmem row
    const float* wrow_ld = W + (size_t)r_ld * ldw;

    const int rA = (R0 >> 3) * H_ + j0 + (R0 & 7);
    const int rB = ((R0 + 1) >> 3) * H_ + j0 + ((R0 + 1) & 7);

    u64 accA[2], accB[2];
    {
        float ba = bias[rA], bb = bias[rB];
        accA[0] = accA[1] = pack2(ba, ba);
        accB[0] = accB[1] = pack2(bb, bb);
    }

    if (K1 == 64)
        accum_64(accA, accB, in1, wrow_ld, s_in, s_w, tid, rs_ld, k8, R0, B0);
    else
        accum_1024(accA, accB, in1, wrow_ld, s_in, s_w, tid, rs_ld, k8, R0, B0);

    if (has2)
        accum_1024(accA, accB, in2, wrow_ld + koff2, s_in, s_w, tid, rs_ld, k8, R0, B0);

    __syncthreads();
    {
        float lo, hi;
        unpack2(accA[0], lo, hi); *(float2*)&s_gates[R0 * 64 + B0]       = make_float2(lo, hi);
        unpack2(accA[1], lo, hi); *(float2*)&s_gates[R0 * 64 + B0 + 2]   = make_float2(lo, hi);
        unpack2(accB[0], lo, hi); *(float2*)&s_gates[(R0 + 1) * 64 + B0]     = make_float2(lo, hi);
        unpack2(accB[1], lo, hi); *(float2*)&s_gates[(R0 + 1) * 64 + B0 + 2] = make_float2(lo, hi);
    }
    __syncthreads();

    // cell update: CHPC*B = 512 elements, CTA-local
    for (int e = tid; e < CHPC * B_; e += NTHREADS) {
        int jjj = e >> 6;
        int b   = e & 63;
        float gi = s_gates[(0 * CHPC + jjj) * 64 + b];
        float gf = s_gates[(1 * CHPC + jjj) * 64 + b];
        float gc = s_gates[(2 * CHPC + jjj) * 64 + b];
        float go = s_gates[(3 * CHPC + jjj) * 64 + b];
        int idx = (j0 + jjj) * B_ + b;
        float cc = c[idx];
        float si = 1.0f / (1.0f + expf(-gi));
        float sf = 1.0f / (1.0f + expf(-gf));
        float so = 1.0f / (1.0f + expf(-go));
        float cn = sf * cc + si * tanhf(gc);
        float hn = so * tanhf(cn);
        c[idx] = cn;
        h_out[idx] = hn;
    }
}

// --------------------------------- kernel ----------------------------------
__global__ void __launch_bounds__(NTHREADS, 1)
rnn_kernel(const float* __restrict__ x,
           const float* __restrict__ W0, const float* __restrict__ b0,
           const float* __restrict__ W1, const float* __restrict__ b1,
           const float* __restrict__ Wf, const float* __restrict__ bf,
           float* __restrict__ out)
{
    extern __shared__ float smem[];
    float* s_in    = smem;                    // 128*64 = 8192 floats
    float* s_w     = s_in + 128 * 64;         // 32*WST = 4224 floats
    float* s_gates = s_w + 32 * WST;          // 32*64  = 2048 floats

    const int tid = threadIdx.x;
    const int cta = blockIdx.x;
    const int j0  = cta * CHPC;

    // ---- Phase 0: init states + transpose x into [t][v][b] ----
    for (int i = cta * NTHREADS + tid; i < H_ * B_; i += NCTA * NTHREADS) {
        g_c0[i] = 0.0f; g_c1[i] = 0.0f;
    }
    for (int i = cta * NTHREADS + tid; i < TIN_ * V_ * B_; i += NCTA * NTHREADS) {
        int t = i / (V_ * B_);
        int rem = i - t * (V_ * B_);
        int v = rem >> 6;
        int b = rem & 63;
        g_xt[i] = x[((size_t)b * TIN_ + t) * V_ + v];
    }
    grid_barrier();

    // ---- Encoder layer 0 ----
    for (int t = 0; t < TIN_; t++) {
        lstm_step(b0,
                  g_xt + (size_t)t * V_ * B_, V_,
                  (t > 0) ? (g_h0all + (size_t)(t - 1) * H_ * B_) : (const float*)0,
                  t > 0, V_,
                  W0, V_ + H_,
                  g_c0, g_h0all + (size_t)t * H_ * B_,
                  s_in, s_w, s_gates, j0);
        grid_barrier();
    }

    // ---- Encoder layer 1 ----
    for (int t = 0; t < TIN_; t++) {
        lstm_step(b1,
                  g_h0all + (size_t)t * H_ * B_, H_,
                  (t > 0) ? g_h1[t & 1] : (const float*)0,
                  t > 0, H_,
                  W1, 2 * H_,
                  g_c1, g_h1[(t + 1) & 1],
                  s_in, s_w, s_gates, j0);
        grid_barrier();
    }

    // ---- Decoder ----
    for (int s = 0; s < TOUT_; s++) {
        const float* in0 = (s == 0) ? (g_xt + (size_t)(TIN_ - 1) * V_ * B_) : g_dec_in;
        const float* h0p = (s == 0) ? (g_h0all + (size_t)(TIN_ - 1) * H_ * B_) : g_dh0[s & 1];
        lstm_step(b0, in0, V_, h0p, true, V_, W0, V_ + H_,
                  g_c0, g_dh0[(s + 1) & 1], s_in, s_w, s_gates, j0);
        grid_barrier();

        const float* h1p = (s == 0) ? g_h1[0] : g_dh1[s & 1];
        lstm_step(b1, g_dh0[(s + 1) & 1], H_, h1p, true, H_, W1, 2 * H_,
                  g_c1, g_dh1[(s + 1) & 1], s_in, s_w, s_gates, j0);
        grid_barrier();

        // projection: out = h1 @ Wf.T + bf  (4096 outputs over 128 CTAs)
        {
            const float* h1 = g_dh1[(s + 1) & 1];
            int o  = cta * 32 + (tid >> 3);
            int ko = tid & 7;
            int v = o >> 6;
            int b = o & 63;
            float sum = 0.0f;
            for (int k = ko; k < H_; k += 8)
                sum += h1[k * B_ + b] * Wf[v * H_ + k];
            sum += __shfl_down_sync(0xFFFFFFFFu, sum, 4, 8);
            sum += __shfl_down_sync(0xFFFFFFFFu, sum, 2, 8);
            sum += __shfl_down_sync(0xFFFFFFFFu, sum, 1, 8);
            if (ko == 0) {
                float val = sum + bf[v];
                out[((size_t)b * TOUT_ + s) * V_ + v] = val;
                g_dec_in[v * B_ + b] = val;
            }
        }
        grid_barrier();
    }
}

// ------------------------------ launch shim --------------------------------
extern "C" void kernel_launch(void* const* d_in, const int* in_sizes, int n_in,
                              void* d_out, int out_size) {
    const float* x  = (const float*)d_in[0];
    const float* W0 = (const float*)d_in[1];
    const float* b0 = (const float*)d_in[2];
    const float* W1 = (const float*)d_in[3];
    const float* b1 = (const float*)d_in[4];
    const float* Wf = (const float*)d_in[5];
    const float* bf = (const float*)d_in[6];

    const int smem_bytes = (128 * 64 + 32 * WST + 32 * 64) * (int)sizeof(float);
    cudaFuncSetAttribute(rnn_kernel, cudaFuncAttributeMaxDynamicSharedMemorySize,
                         smem_bytes);
    rnn_kernel<<<NCTA, NTHREADS, smem_bytes>>>(x, W0, b0, W1, b1, Wf, bf,
                                               (float*)d_out);
}

// round 10
// speedup vs baseline: 6.2023x; 2.5701x over previous
#include <cuda_runtime.h>
#include <cuda_bf16.h>
#include <cstdint>

#define NCTA 64
#define NTH  256
#define B_   64
#define TIN  256
#define V_   64
#define H_   1024
#define TOUT 32
#define NQ0  9
#define NQ1  16
#define CHE  16384   // bf16 elems per packed chunk (32 KB, incl hi/lo)
#define NST  66      // reduction smem n-stride (floats)

typedef __nv_bfloat16 bf16;

// ----------------------------- device scratch ------------------------------
__device__ bf16 g_A0[(size_t)NCTA * NQ0 * CHE];
__device__ bf16 g_A1[(size_t)NCTA * NQ1 * CHE];
__device__ bf16 g_xpk[(size_t)TIN * CHE];
__device__ bf16 g_h0pk[2][8 * CHE];
__device__ bf16 g_h1pk[2][8 * CHE];
__device__ bf16 g_dinpk[CHE];
__device__ float g_h1f[B_ * H_];
__device__ float g_c0[H_ * B_], g_c1[H_ * B_];
__device__ unsigned g_bc = 0;
__device__ volatile unsigned g_bg = 0;

// ------------------------------ grid barrier -------------------------------
__device__ __forceinline__ void grid_barrier() {
    __syncthreads();
    if (threadIdx.x == 0) {
        unsigned gen = g_bg;
        __threadfence();
        unsigned t = atomicAdd(&g_bc, 1u);
        if (t == NCTA - 1) { g_bc = 0; __threadfence(); g_bg = gen + 1; }
        else while (g_bg == gen) { }
        __threadfence();
    }
    __syncthreads();
}

// ------------------------------- helpers -----------------------------------
__device__ __forceinline__ void bfsplit(float v, bf16& h, bf16& l) {
    h = __float2bfloat16(v);
    l = __float2bfloat16(v - __bfloat162float(h));
}

// fragment-linear B-pack elem index for (k in [0,128), n in [0,64), hl)
__device__ __forceinline__ int bpk_idx(int k, int n, int hl) {
    int s = k >> 4, kk = k & 15;
    int r = kk >> 3, tq = (kk & 7) >> 1, e = kk & 1;
    int f = n >> 3, tl = (n & 7) * 4 + tq;
    return (s * 2 + hl) * 1024 + (f >> 1) * 256 + tl * 8 + (f & 1) * 4 + r * 2 + e;
}

__device__ __forceinline__ void pack_h(bf16* pk, int j, int b, float v) {
    bf16 h, l; bfsplit(v, h, l);
    int ch = j >> 7, k = j & 127;
    pk[ch * CHE + bpk_idx(k, b, 0)] = h;
    pk[ch * CHE + bpk_idx(k, b, 1)] = l;
}

__device__ __forceinline__ void mma16816(float* d, const uint32_t* a, const uint32_t* b) {
    asm volatile(
        "mma.sync.aligned.m16n8k16.row.col.f32.bf16.bf16.f32 "
        "{%0,%1,%2,%3}, {%4,%5,%6,%7}, {%8,%9}, {%0,%1,%2,%3};"
        : "+f"(d[0]), "+f"(d[1]), "+f"(d[2]), "+f"(d[3])
        : "r"(a[0]), "r"(a[1]), "r"(a[2]), "r"(a[3]), "r"(b[0]), "r"(b[1]));
}

// ---------------------------------------------------------------------------
// One LSTM step. Warp (kq = wid&3, mh = wid>>2): k16s {2kq, 2kq+1} per chunk,
// m-tiles {2mh, 2mh+1}. 3-pass bf16-split HMMA, fp32 accum, smem K-reduce,
// CTA-local cell update, fragment-packed h output.
// ---------------------------------------------------------------------------
__device__ void mma_step(const bf16* __restrict__ Ab, int nq,
                         const bf16* __restrict__ Bfst, int nfst,
                         const bf16* __restrict__ Bsnd,
                         const float* __restrict__ bias,
                         float* __restrict__ cst,
                         bf16* __restrict__ hpk, float* __restrict__ h1f,
                         float* red, int cta)
{
    const int tid = threadIdx.x, wid = tid >> 5, lane = tid & 31;
    const int kq = wid & 3, mh = wid >> 2;
    const int t4 = lane >> 2, tq = lane & 3;

    float acc[2][8][4];
    #pragma unroll
    for (int j = 0; j < 2; j++) {
        float b0v = bias[(mh * 2 + j) * 1024 + cta * 16 + t4];
        float b1v = bias[(mh * 2 + j) * 1024 + cta * 16 + t4 + 8];
        #pragma unroll
        for (int f = 0; f < 8; f++) {
            acc[j][f][0] = b0v; acc[j][f][1] = b0v;
            acc[j][f][2] = b1v; acc[j][f][3] = b1v;
        }
    }

    uint32_t a[2][2][2][4];   // [buf][j][hl][reg]
    uint32_t bb[2][2][8][2];  // [buf][hl][f][reg]

    const int nqq = nq * 2;
    #define LOADOPS(qq, buf) do {                                               \
        int _q = (qq) >> 1, _s = kq * 2 + ((qq) & 1);                           \
        const bf16* _A = Ab + (size_t)_q * CHE;                                 \
        const bf16* _B = (_q < nfst) ? (Bfst + (size_t)_q * CHE)                \
                                     : (Bsnd + (size_t)(_q - nfst) * CHE);      \
        _Pragma("unroll")                                                       \
        for (int _j = 0; _j < 2; _j++)                                          \
            _Pragma("unroll")                                                   \
            for (int _hl = 0; _hl < 2; _hl++) {                                 \
                uint4 _v = *(const uint4*)(_A +                                 \
                    (((_s * 4 + (mh * 2 + _j)) * 2 + _hl) * 256 + lane * 8));   \
                a[buf][_j][_hl][0] = _v.x; a[buf][_j][_hl][1] = _v.y;           \
                a[buf][_j][_hl][2] = _v.z; a[buf][_j][_hl][3] = _v.w;           \
            }                                                                   \
        _Pragma("unroll")                                                       \
        for (int _hl = 0; _hl < 2; _hl++)                                       \
            _Pragma("unroll")                                                   \
            for (int _ii = 0; _ii < 4; _ii++) {                                 \
                uint4 _v = *(const uint4*)(_B +                                 \
                    ((_s * 2 + _hl) * 1024 + _ii * 256 + lane * 8));            \
                bb[buf][_hl][2 * _ii][0] = _v.x; bb[buf][_hl][2 * _ii][1] = _v.y; \
                bb[buf][_hl][2 * _ii + 1][0] = _v.z;                            \
                bb[buf][_hl][2 * _ii + 1][1] = _v.w;                            \
            }                                                                   \
    } while (0)

    LOADOPS(0, 0);
    #pragma unroll 2
    for (int qq = 0; qq < nqq; qq++) {
        const int buf = qq & 1;
        if (qq + 1 < nqq) LOADOPS(qq + 1, buf ^ 1);
        #pragma unroll
        for (int j = 0; j < 2; j++)
            #pragma unroll
            for (int f = 0; f < 8; f++) {
                mma16816(acc[j][f], a[buf][j][0], bb[buf][0][f]);   // hi*hi
                mma16816(acc[j][f], a[buf][j][0], bb[buf][1][f]);   // hi*lo
                mma16816(acc[j][f], a[buf][j][1], bb[buf][0][f]);   // lo*hi
            }
    }
    #undef LOADOPS

    // K-split partial store
    #pragma unroll
    for (int j = 0; j < 2; j++) {
        int mb = (mh * 2 + j) * 16 + t4;
        #pragma unroll
        for (int f = 0; f < 8; f++) {
            int n = f * 8 + tq * 2;
            *(float2*)&red[(kq * 64 + mb) * NST + n]     = make_float2(acc[j][f][0], acc[j][f][1]);
            *(float2*)&red[(kq * 64 + mb + 8) * NST + n] = make_float2(acc[j][f][2], acc[j][f][3]);
        }
    }
    __syncthreads();

    // reduce 4 partials + cell update (CTA owns 16 channels x 64 batches)
    #pragma unroll
    for (int z = 0; z < 4; z++) {
        int it = tid + z * 256;
        int ch = it >> 6, b = it & 63;
        float g[4];
        #pragma unroll
        for (int gg = 0; gg < 4; gg++) {
            int m = gg * 16 + ch;
            float sv = 0.f;
            #pragma unroll
            for (int k2 = 0; k2 < 4; k2++) sv += red[(k2 * 64 + m) * NST + b];
            g[gg] = sv;
        }
        int j = cta * 16 + ch;
        float cc = cst[j * 64 + b];
        float si = 1.f / (1.f + expf(-g[0]));
        float sf = 1.f / (1.f + expf(-g[1]));
        float so = 1.f / (1.f + expf(-g[3]));
        float cn = sf * cc + si * tanhf(g[2]);
        float hn = so * tanhf(cn);
        cst[j * 64 + b] = cn;
        pack_h(hpk, j, b, hn);
        if (h1f) h1f[b * 1024 + j] = hn;
    }
}

// --------------------------------- kernel ----------------------------------
__global__ void __launch_bounds__(NTH, 1)
rnn_kernel(const float* __restrict__ x,
           const float* __restrict__ W0, const float* __restrict__ b0,
           const float* __restrict__ W1, const float* __restrict__ b1,
           const float* __restrict__ Wf, const float* __restrict__ bfv,
           float* __restrict__ out)
{
    extern __shared__ float red[];   // [4][64][NST]
    const int tid = threadIdx.x, cta = blockIdx.x;
    const int gid = cta * NTH + tid, gs = NCTA * NTH;

    // ---- prologue ----
    for (int i = gid; i < H_ * B_; i += gs) { g_c0[i] = 0.f; g_c1[i] = 0.f; }
    // x -> fragment pack (k<64) + zero pad (k 64..127)
    for (int i = gid; i < TIN * 64 * 64; i += gs) {
        int n = i & 63, k = (i >> 6) & 63, tt = i >> 12;
        float v = x[((size_t)n * TIN + tt) * 64 + k];
        bf16 h, l; bfsplit(v, h, l);
        g_xpk[(size_t)tt * CHE + bpk_idx(k, n, 0)] = h;
        g_xpk[(size_t)tt * CHE + bpk_idx(k, n, 1)] = l;
    }
    for (int i = gid; i < TIN * 8192; i += gs) {
        int tt = i >> 13, e = i & 8191;
        g_xpk[(size_t)tt * CHE + 8192 + e] = __float2bfloat16(0.f);
    }
    for (int i = gid; i < 8192; i += gs) g_dinpk[8192 + i] = __float2bfloat16(0.f);
    // W0 -> A0 pack (K layout: [x 0-63 | zeros 64-127 | h 128-1151])
    for (int i = gid; i < NCTA * NQ0 * 8192; i += gs) {
        int p = i & 7, t = (i >> 3) & 31, mt = (i >> 8) & 3, s = (i >> 10) & 7;
        int rest = i >> 13;
        int chk = rest % NQ0, c2 = rest / NQ0;
        int r = p >> 1, e = p & 1;
        int row = (t >> 2) + 8 * (r & 1);
        int koff = 2 * (t & 3) + e + 8 * (r >> 1);
        int m = mt * 16 + row;
        int grow = (m >> 4) * 1024 + c2 * 16 + (m & 15);
        int kg = chk * 128 + s * 16 + koff;
        float w = 0.f;
        if (kg < 64)        w = W0[(size_t)grow * 1088 + kg];
        else if (kg >= 128) w = W0[(size_t)grow * 1088 + kg - 64];
        bf16 h, l; bfsplit(w, h, l);
        size_t base = ((((size_t)(c2 * NQ0 + chk) * 8 + s) * 4 + mt) * 2) * 256 + t * 8 + p;
        g_A0[base] = h;
        g_A0[base + 256] = l;
    }
    // W1 -> A1 pack
    for (int i = gid; i < NCTA * NQ1 * 8192; i += gs) {
        int p = i & 7, t = (i >> 3) & 31, mt = (i >> 8) & 3, s = (i >> 10) & 7;
        int rest = i >> 13;
        int chk = rest & 15, c2 = rest >> 4;
        int r = p >> 1, e = p & 1;
        int row = (t >> 2) + 8 * (r & 1);
        int koff = 2 * (t & 3) + e + 8 * (r >> 1);
        int m = mt * 16 + row;
        int grow = (m >> 4) * 1024 + c2 * 16 + (m & 15);
        int kg = chk * 128 + s * 16 + koff;
        float w = W1[(size_t)grow * 2048 + kg];
        bf16 h, l; bfsplit(w, h, l);
        size_t base = ((((size_t)(c2 * NQ1 + chk) * 8 + s) * 4 + mt) * 2) * 256 + t * 8 + p;
        g_A1[base] = h;
        g_A1[base + 256] = l;
    }
    grid_barrier();

    const bf16* A0c = g_A0 + (size_t)cta * NQ0 * CHE;
    const bf16* A1c = g_A1 + (size_t)cta * NQ1 * CHE;

    // ---- encoder ----
    for (int tt = 0; tt < TIN; tt++) {
        mma_step(A0c, tt == 0 ? 1 : NQ0, g_xpk + (size_t)tt * CHE, 1,
                 g_h0pk[(tt + 1) & 1], b0, g_c0, g_h0pk[tt & 1], (float*)0, red, cta);
        grid_barrier();
        mma_step(A1c, tt == 0 ? 8 : NQ1, g_h0pk[tt & 1], 8, g_h1pk[(tt + 1) & 1],
                 b1, g_c1, g_h1pk[tt & 1], (float*)0, red, cta);
        grid_barrier();
    }

    // ---- decoder ----
    for (int s = 0; s < TOUT; s++) {
        const bf16* din = (s == 0) ? (g_xpk + (size_t)(TIN - 1) * CHE) : g_dinpk;
        mma_step(A0c, NQ0, din, 1, g_h0pk[(s + 1) & 1],
                 b0, g_c0, g_h0pk[s & 1], (float*)0, red, cta);
        grid_barrier();
        mma_step(A1c, NQ1, g_h0pk[s & 1], 8, g_h1pk[(s + 1) & 1],
                 b1, g_c1, g_h1pk[s & 1], g_h1f, red, cta);
        grid_barrier();
        // projection: out = h1 @ Wf.T + bf  (4096 outs over 64 CTAs, 4-lane K-split)
        {
            int o = cta * 64 + (tid >> 2);
            int v = o >> 6, b = o & 63, ko = tid & 3;
            const float4* hr = (const float4*)(g_h1f + (size_t)b * 1024);
            const float4* wr = (const float4*)(Wf + (size_t)v * 1024);
            float sum = 0.f;
            for (int k = ko; k < 256; k += 4) {
                float4 hv = hr[k], wv = wr[k];
                sum += hv.x * wv.x + hv.y * wv.y + hv.z * wv.z + hv.w * wv.w;
            }
            sum += __shfl_xor_sync(0xffffffffu, sum, 1);
            sum += __shfl_xor_sync(0xffffffffu, sum, 2);
            if (ko == 0) {
                float val = sum + bfv[v];
                out[((size_t)b * TOUT + s) * 64 + v] = val;
                bf16 h, l; bfsplit(val, h, l);
                g_dinpk[bpk_idx(v, b, 0)] = h;
                g_dinpk[bpk_idx(v, b, 1)] = l;
            }
        }
        grid_barrier();
    }
}

// ------------------------------ launch shim --------------------------------
extern "C" void kernel_launch(void* const* d_in, const int* in_sizes, int n_in,
                              void* d_out, int out_size) {
    const float* x  = (const float*)d_in[0];
    const float* W0 = (const float*)d_in[1];
    const float* b0 = (const float*)d_in[2];
    const float* W1 = (const float*)d_in[3];
    const float* b1 = (const float*)d_in[4];
    const float* Wf = (const float*)d_in[5];
    const float* bf = (const float*)d_in[6];
    const int smem_bytes = 4 * 64 * NST * (int)sizeof(float);
    cudaFuncSetAttribute(rnn_kernel, cudaFuncAttributeMaxDynamicSharedMemorySize,
                         smem_bytes);
    rnn_kernel<<<NCTA, NTH, smem_bytes>>>(x, W0, b0, W1, b1, Wf, bf, (float*)d_out);
}